// round 10
// baseline (speedup 1.0000x reference)
#include <cuda_runtime.h>
#include <cuda_fp16.h>
#include <cstdint>

// ---------------------------------------------------------------------------
#define M_ 16384           // B*S token rows
#define P_ 512             // prototypes (= N)
#define D_ 768             // feature dim (= K)
#define BM 128
#define BN 128
#define BKH 64             // K halves per stage (128 B per row)
#define NSST 12            // stages per tile (D_/BKH)
#define NTILES 512         // (M_/BM) * (P_/BN)
#define GRID 296           // persistent CTAs (2 per SM)
#define NTH 160            // 4 consumer warps + 1 producer warp
#define RING 3
#define ATILEB 16384       // A tile: 128 rows x 128 B
#define STAGEB 32768       // A + B
#define OFF_MB (RING * STAGEB)          // full[i]=+16i, empty[i]=+16i+8
#define OFF_IDB (OFF_MB + RING * 16)    // 2 x int tile-id slots
#define SMEM_BYTES (OFF_IDB + 64 + 128)

__device__ __half g_a16[(size_t)M_ * D_];
__device__ __half g_b16[(size_t)P_ * D_];
__device__ float  g_xsq[M_];
__device__ float  g_psq[P_];
__device__ int    g_ctr;

// ---------------------------------------------------------------------------
// Prep: one pass -> fp16 copies + exact f32 row norms + prototype passthrough.
// Also resets the persistent-tile queue counter (GEMM runs after, same stream).
// ---------------------------------------------------------------------------
__global__ void prep_kernel(const float* __restrict__ X,
                            const float* __restrict__ Pp,
                            float* __restrict__ proto_out) {
    if (blockIdx.x == 0 && threadIdx.x == 0) g_ctr = GRID;
    const int r   = threadIdx.x >> 4;
    const int kq  = threadIdx.x & 15;
    const int row = blockIdx.x * 16 + r;
    const float* src;
    __half* dst16;
    float* dstn;
    float* passthru = nullptr;
    if (row < M_) {
        src = X + (size_t)row * D_;  dst16 = g_a16 + (size_t)row * D_;  dstn = g_xsq + row;
    } else {
        const int pr = row - M_;
        src = Pp + (size_t)pr * D_;  dst16 = g_b16 + (size_t)pr * D_;   dstn = g_psq + pr;
        passthru = proto_out + (size_t)pr * D_;
    }
    float s = 0.f;
    #pragma unroll
    for (int i = 0; i < 12; i++) {
        float4 v = *reinterpret_cast<const float4*>(src + i * 64 + kq * 4);
        s = fmaf(v.x, v.x, fmaf(v.y, v.y, fmaf(v.z, v.z, fmaf(v.w, v.w, s))));
        __half2 h01 = __floats2half2_rn(v.x, v.y);
        __half2 h23 = __floats2half2_rn(v.z, v.w);
        *reinterpret_cast<uint2*>(dst16 + i * 64 + kq * 4) =
            make_uint2(*reinterpret_cast<uint32_t*>(&h01),
                       *reinterpret_cast<uint32_t*>(&h23));
        if (passthru) *reinterpret_cast<float4*>(passthru + i * 64 + kq * 4) = v;
    }
    #pragma unroll
    for (int o = 8; o; o >>= 1) s += __shfl_xor_sync(0xffffffffu, s, o);
    if (kq == 0) *dstn = s;
}

// ---------------------------------------------------------------------------
__device__ __forceinline__ void cp_async16(uint32_t d, const void* s) {
    asm volatile("cp.async.cg.shared.global [%0], [%1], 16;" ::"r"(d), "l"(s));
}
#define CPA_MBAR(a) \
    asm volatile("cp.async.mbarrier.arrive.noinc.shared.b64 [%0];" :: "r"(a) : "memory")
#define MBAR_INIT(a, n) \
    asm volatile("mbarrier.init.shared.b64 [%0], %1;" :: "r"(a), "r"(n) : "memory")
#define MBAR_ARRIVE(a) \
    asm volatile("mbarrier.arrive.shared.b64 _, [%0];" :: "r"(a) : "memory")
#define MBAR_WAIT(a, ph) do {                                                   \
    asm volatile("{\n\t.reg .pred P1;\n\t"                                       \
        "WL_%=:\n\tmbarrier.try_wait.parity.acquire.cta.shared::cta.b64 P1, [%0], %1, 0x989680;\n\t" \
        "@P1 bra.uni WD_%=;\n\tbra.uni WL_%=;\n\tWD_%=:\n\t}"                    \
        :: "r"(a), "r"(ph) : "memory");                                          \
} while (0)

#define LDSM_X4(r0, r1, r2, r3, a)                                             \
    asm volatile("ldmatrix.sync.aligned.m8n8.x4.shared.b16 {%0,%1,%2,%3}, [%4];" \
                 : "=r"(r0), "=r"(r1), "=r"(r2), "=r"(r3) : "r"(a))

#define MMA_F16(c0, c1, c2, c3, a0, a1, a2, a3, b0, b1)                        \
    asm volatile("mma.sync.aligned.m16n8k16.row.col.f32.f16.f16.f32 "          \
                 "{%0,%1,%2,%3}, {%4,%5,%6,%7}, {%8,%9}, {%0,%1,%2,%3};"       \
                 : "+f"(c0), "+f"(c1), "+f"(c2), "+f"(c3)                      \
                 : "r"(a0), "r"(a1), "r"(a2), "r"(a3), "r"(b0), "r"(b1))

// ---------------------------------------------------------------------------
// Warp-specialized persistent distance GEMM:
//   C[m][n] = xsq[m] + psq[n] - 2 * sum_k A16[m][k] * B16[n][k]
// Warps 0-3: consumers (64x64 warp tiles over a 128x128 CTA tile).
// Warp 4:    producer (cp.async into 3-slot ring, mbarrier handshake).
// Tiles pulled from a global atomic queue (counter pre-set by prep_kernel).
// Smem per stage tile: row r (128 B), 16B unit u stored at (u ^ (r & 7)).
// ---------------------------------------------------------------------------
__global__ __launch_bounds__(NTH, 2)
void dist_f16_ws_kernel(float* __restrict__ C) {
    extern __shared__ __align__(16) char smem[];
    uint32_t sb0;
    asm("{ .reg .u64 t; cvta.to.shared.u64 t, %1; cvt.u32.u64 %0, t; }"
        : "=r"(sb0) : "l"(smem));
    const uint32_t sb = (sb0 + 127u) & ~127u;
    char* sg = smem + (sb - sb0);            // generic alias of aligned base

    const int tid  = threadIdx.x;
    const int lane = tid & 31;
    const int warp = tid >> 5;

    if (tid == 0) {
        #pragma unroll
        for (int i = 0; i < RING; i++) {
            MBAR_INIT(sb + OFF_MB + i * 16,     33);   // full: 32 cp + 1 plain
            MBAR_INIT(sb + OFF_MB + i * 16 + 8, 128);  // empty: 128 consumers
        }
    }
    __syncthreads();

    volatile int* idbuf = reinterpret_cast<volatile int*>(sg + OFF_IDB);

    if (warp == 4) {
        // ================= producer =================
        const int prow = lane * 4;           // 4 rows per lane
        int tile = blockIdx.x;
        int n = 0;
        int pslot = 0, pph = 1;              // empty-waits pass for first ring
        for (;;) {
            if (tile >= NTILES) {            // sentinel stage
                MBAR_WAIT(sb + OFF_MB + pslot * 16 + 8, pph);
                if (lane == 0) idbuf[n & 1] = -1;
                MBAR_ARRIVE(sb + OFF_MB + pslot * 16);
                if (lane == 0) MBAR_ARRIVE(sb + OFF_MB + pslot * 16);
                break;
            }
            const __half* Ablk = g_a16 + (size_t)(tile >> 2) * BM * D_;
            const __half* Bblk = g_b16 + (size_t)(tile & 3) * BN * D_;
            for (int s = 0; s < NSST; s++) {
                MBAR_WAIT(sb + OFF_MB + pslot * 16 + 8, pph);
                if (s == 0 && lane == 0) idbuf[n & 1] = tile;
                const uint32_t ab = sb + (uint32_t)pslot * STAGEB;
                const uint32_t bb = ab + ATILEB;
                const int kf = s * BKH;
                #pragma unroll
                for (int j = 0; j < 32; j++) {
                    const int row = prow + (j >> 3);
                    const int col = j & 7;
                    const uint32_t so = (uint32_t)row * 128
                                      + (uint32_t)((col ^ (row & 7)) << 4);
                    cp_async16(ab + so, Ablk + (size_t)row * D_ + kf + col * 8);
                    cp_async16(bb + so, Bblk + (size_t)row * D_ + kf + col * 8);
                }
                CPA_MBAR(sb + OFF_MB + pslot * 16);
                if (lane == 0) MBAR_ARRIVE(sb + OFF_MB + pslot * 16);
                if (++pslot == RING) { pslot = 0; pph ^= 1; }
            }
            n++;
            if (lane == 0) tile = atomicAdd(&g_ctr, 1);
            tile = __shfl_sync(0xffffffffu, tile, 0);
        }
        return;
    }

    // ================= consumers (warps 0-3) =================
    const int wm = warp & 1;                 // 2 warps along M -> 64 rows
    const int wn = warp >> 1;                // 2 warps along N -> 64 cols
    const int rA = wm * 64 + (lane & 7) + ((lane >> 3) & 1) * 8;   // + i*16
    const int uA = lane >> 4;
    const int rB = wn * 64 + (lane & 7) + (lane >> 4) * 8;         // + jp*16
    const int uB = (lane >> 3) & 1;
    const uint32_t swz = (uint32_t)(lane & 7);
    const int g = lane >> 2;
    const int t = lane & 3;

    float c[4][8][4];
    #pragma unroll
    for (int i = 0; i < 4; i++)
        #pragma unroll
        for (int j = 0; j < 8; j++)
            #pragma unroll
            for (int q = 0; q < 4; q++) c[i][j][q] = 0.f;

    uint32_t a[2][4][4], b[2][4][4];
    int slot = 0, ph = 0, n = 0;

    for (;;) {
        MBAR_WAIT(sb + OFF_MB + slot * 16, ph);      // first stage of tile
        const int id = idbuf[n & 1];
        if (id < 0) break;
        const int by = id >> 2;
        const int bx = id & 3;

        for (int s = 0; s < NSST; s++) {
            if (s) MBAR_WAIT(sb + OFF_MB + slot * 16, ph);
            const uint32_t ab = sb + (uint32_t)slot * STAGEB;
            const uint32_t bb = ab + ATILEB;

            // kk=0 fragments
            #pragma unroll
            for (int i = 0; i < 4; i++) {
                const uint32_t addr = ab + (uint32_t)(rA + i * 16) * 128
                    + ((((uint32_t)uA) ^ swz) << 4);
                LDSM_X4(a[0][i][0], a[0][i][1], a[0][i][2], a[0][i][3], addr);
            }
            #pragma unroll
            for (int jp = 0; jp < 4; jp++) {
                const uint32_t addr = bb + (uint32_t)(rB + jp * 16) * 128
                    + ((((uint32_t)uB) ^ swz) << 4);
                LDSM_X4(b[0][jp][0], b[0][jp][1], b[0][jp][2], b[0][jp][3], addr);
            }
            #pragma unroll
            for (int kk = 0; kk < 4; kk++) {
                const int fb = kk & 1;
                if (kk + 1 < 4) {                     // prefetch next k16
                    #pragma unroll
                    for (int i = 0; i < 4; i++) {
                        const uint32_t addr = ab + (uint32_t)(rA + i * 16) * 128
                            + ((((uint32_t)((kk + 1) * 2 + uA)) ^ swz) << 4);
                        LDSM_X4(a[fb ^ 1][i][0], a[fb ^ 1][i][1],
                                a[fb ^ 1][i][2], a[fb ^ 1][i][3], addr);
                    }
                    #pragma unroll
                    for (int jp = 0; jp < 4; jp++) {
                        const uint32_t addr = bb + (uint32_t)(rB + jp * 16) * 128
                            + ((((uint32_t)((kk + 1) * 2 + uB)) ^ swz) << 4);
                        LDSM_X4(b[fb ^ 1][jp][0], b[fb ^ 1][jp][1],
                                b[fb ^ 1][jp][2], b[fb ^ 1][jp][3], addr);
                    }
                }
                #pragma unroll
                for (int i = 0; i < 4; i++) {
                    #pragma unroll
                    for (int jp = 0; jp < 4; jp++) {
                        MMA_F16(c[i][jp * 2][0], c[i][jp * 2][1],
                                c[i][jp * 2][2], c[i][jp * 2][3],
                                a[fb][i][0], a[fb][i][1], a[fb][i][2], a[fb][i][3],
                                b[fb][jp][0], b[fb][jp][1]);
                        MMA_F16(c[i][jp * 2 + 1][0], c[i][jp * 2 + 1][1],
                                c[i][jp * 2 + 1][2], c[i][jp * 2 + 1][3],
                                a[fb][i][0], a[fb][i][1], a[fb][i][2], a[fb][i][3],
                                b[fb][jp][2], b[fb][jp][3]);
                    }
                }
            }
            MBAR_ARRIVE(sb + OFF_MB + slot * 16 + 8);   // stage consumed
            if (++slot == RING) { slot = 0; ph ^= 1; }
        }

        // ---- epilogue: dist = xsq + psq - 2*cross ----
        #pragma unroll
        for (int i = 0; i < 4; i++) {
            const int mg0 = by * BM + wm * 64 + i * 16 + g;
            const float x0 = g_xsq[mg0];
            const float x1 = g_xsq[mg0 + 8];
            float* row0 = C + (size_t)mg0 * P_;
            float* row1 = C + (size_t)(mg0 + 8) * P_;
            #pragma unroll
            for (int j = 0; j < 8; j++) {
                const int ng = bx * BN + wn * 64 + j * 8 + 2 * t;
                const float p0 = g_psq[ng];
                const float p1 = g_psq[ng + 1];
                float2 v0, v1;
                v0.x = x0 + p0 - 2.f * c[i][j][0];
                v0.y = x0 + p1 - 2.f * c[i][j][1];
                v1.x = x1 + p0 - 2.f * c[i][j][2];
                v1.y = x1 + p1 - 2.f * c[i][j][3];
                *reinterpret_cast<float2*>(row0 + ng) = v0;
                *reinterpret_cast<float2*>(row1 + ng) = v1;
                c[i][j][0] = 0.f; c[i][j][1] = 0.f;
                c[i][j][2] = 0.f; c[i][j][3] = 0.f;
            }
        }
        n++;
    }
}

// ---------------------------------------------------------------------------
extern "C" void kernel_launch(void* const* d_in, const int* in_sizes, int n_in,
                              void* d_out, int out_size) {
    const float* inputs = (const float*)d_in[0];   // [M_, D_]
    const float* protos = (const float*)d_in[1];   // [P_, D_]
    float* out = (float*)d_out;

    // 1) fp16 copies + exact f32 norms + passthrough + queue reset
    prep_kernel<<<(M_ + P_) / 16, 256>>>(inputs, protos, out + (size_t)M_ * P_);

    // 2) warp-specialized persistent distance GEMM
    cudaFuncSetAttribute(dist_f16_ws_kernel,
                         cudaFuncAttributeMaxDynamicSharedMemorySize, SMEM_BYTES);
    dist_f16_ws_kernel<<<GRID, NTH, SMEM_BYTES>>>(out);
}

// round 11
// speedup vs baseline: 1.4819x; 1.4819x over previous
#include <cuda_runtime.h>
#include <cuda_fp16.h>
#include <cstdint>

// ---------------------------------------------------------------------------
#define M_ 16384           // B*S token rows
#define P_ 512             // prototypes (= N)
#define D_ 768             // feature dim (= K)
#define BM 128
#define BN 128
#define BKH 64             // K halves per stage (128 B per row)
#define NSST 12            // stages per tile
#define NTILES 512
#define GRID 296           // persistent CTAs (2 per SM)
#define NTH 128            // 4 warps
#define RING 3
#define ATILEB 16384
#define STAGEB 32768       // A + B per stage
#define SMEM_BYTES (RING * STAGEB + 128)

__device__ __half g_a16[(size_t)M_ * D_];
__device__ __half g_b16[(size_t)P_ * D_];
__device__ float  g_xsq[M_];
__device__ float  g_psq[P_];

// ---------------------------------------------------------------------------
// Prep: one pass -> fp16 copies + exact f32 row norms + prototype passthrough.
// ---------------------------------------------------------------------------
__global__ void prep_kernel(const float* __restrict__ X,
                            const float* __restrict__ Pp,
                            float* __restrict__ proto_out) {
    const int r   = threadIdx.x >> 4;
    const int kq  = threadIdx.x & 15;
    const int row = blockIdx.x * 16 + r;
    const float* src;
    __half* dst16;
    float* dstn;
    float* passthru = nullptr;
    if (row < M_) {
        src = X + (size_t)row * D_;  dst16 = g_a16 + (size_t)row * D_;  dstn = g_xsq + row;
    } else {
        const int pr = row - M_;
        src = Pp + (size_t)pr * D_;  dst16 = g_b16 + (size_t)pr * D_;   dstn = g_psq + pr;
        passthru = proto_out + (size_t)pr * D_;
    }
    float s = 0.f;
    #pragma unroll
    for (int i = 0; i < 12; i++) {
        float4 v = *reinterpret_cast<const float4*>(src + i * 64 + kq * 4);
        s = fmaf(v.x, v.x, fmaf(v.y, v.y, fmaf(v.z, v.z, fmaf(v.w, v.w, s))));
        __half2 h01 = __floats2half2_rn(v.x, v.y);
        __half2 h23 = __floats2half2_rn(v.z, v.w);
        *reinterpret_cast<uint2*>(dst16 + i * 64 + kq * 4) =
            make_uint2(*reinterpret_cast<uint32_t*>(&h01),
                       *reinterpret_cast<uint32_t*>(&h23));
        if (passthru) *reinterpret_cast<float4*>(passthru + i * 64 + kq * 4) = v;
    }
    #pragma unroll
    for (int o = 8; o; o >>= 1) s += __shfl_xor_sync(0xffffffffu, s, o);
    if (kq == 0) *dstn = s;
}

// ---------------------------------------------------------------------------
__device__ __forceinline__ void cp_async16(uint32_t d, const void* s) {
    asm volatile("cp.async.cg.shared.global [%0], [%1], 16;" ::"r"(d), "l"(s));
}
#define CP_COMMIT() asm volatile("cp.async.commit_group;" ::: "memory")
#define CP_WAIT_1() asm volatile("cp.async.wait_group 1;" ::: "memory")

#define LDSM_X4(r0, r1, r2, r3, a)                                             \
    asm volatile("ldmatrix.sync.aligned.m8n8.x4.shared.b16 {%0,%1,%2,%3}, [%4];" \
                 : "=r"(r0), "=r"(r1), "=r"(r2), "=r"(r3) : "r"(a))

#define MMA_F16(c0, c1, c2, c3, a0, a1, a2, a3, b0, b1)                        \
    asm volatile("mma.sync.aligned.m16n8k16.row.col.f32.f16.f16.f32 "          \
                 "{%0,%1,%2,%3}, {%4,%5,%6,%7}, {%8,%9}, {%0,%1,%2,%3};"       \
                 : "+f"(c0), "+f"(c1), "+f"(c2), "+f"(c3)                      \
                 : "r"(a0), "r"(a1), "r"(a2), "r"(a3), "r"(b0), "r"(b1))

// ---------------------------------------------------------------------------
// Persistent fused distance GEMM, fp16 tensor cores. 4 warps (2x2), warp tile
// 64x64, CTA tile 128x128, 2 CTAs/SM. CTA c statically owns tiles c, c+GRID;
// the cp.async ring runs on a linear stage counter so the next tile's loads
// overlap the current tile's tail stages AND its epilogue.
//   C[m][n] = xsq[m] + psq[n] - 2 * sum_k A16[m][k] * B16[n][k]
// Smem per stage tile: row r (128 B), 16B unit u stored at (u ^ (r & 7)).
// ---------------------------------------------------------------------------
__global__ __launch_bounds__(NTH, 2)
void dist_f16_p_kernel(float* __restrict__ C) {
    extern __shared__ __align__(16) char smem[];
    uint32_t sb0;
    asm("{ .reg .u64 t; cvta.to.shared.u64 t, %1; cvt.u32.u64 %0, t; }"
        : "=r"(sb0) : "l"(smem));
    const uint32_t sb = (sb0 + 127u) & ~127u;

    const int tid  = threadIdx.x;
    const int lane = tid & 31;
    const int warp = tid >> 5;
    const int wm   = warp & 1;       // 2 warps along M -> 64 rows each
    const int wn   = warp >> 1;      // 2 warps along N -> 64 cols each
    const int cta  = blockIdx.x;

    const int nt = (cta + GRID < NTILES) ? 2 : 1;
    int ids[2];
    ids[0] = cta;
    ids[1] = cta + GRID;

    // loader mapping: A 1024 + B 1024 16B-units per stage -> 8 + 8 per thread
    const int lrow = tid >> 3;       // 0..15 (j adds 16)
    const int lu   = tid & 7;
    const uint32_t lsw = (uint32_t)((lu ^ (lrow & 7)) << 4);

    auto load_stage = [&](int w, int s, int slot) {
        const int id = ids[w];
        const __half* Ablk = g_a16 + (size_t)(id >> 2) * BM * D_;
        const __half* Bblk = g_b16 + (size_t)(id & 3) * BN * D_;
        const uint32_t ab = sb + (uint32_t)slot * STAGEB;
        const uint32_t bb = ab + ATILEB;
        const int kf = s * BKH + lu * 8;
        #pragma unroll
        for (int j = 0; j < 8; j++) {
            const int row = lrow + j * 16;
            cp_async16(ab + (uint32_t)row * 128 + lsw,
                       Ablk + (size_t)row * D_ + kf);
            cp_async16(bb + (uint32_t)row * 128 + lsw,
                       Bblk + (size_t)row * D_ + kf);
        }
    };

    // ldmatrix per-lane components
    const int rA = wm * 64 + (lane & 7) + ((lane >> 3) & 1) * 8;   // + i*16
    const int uA = lane >> 4;
    const int rB = wn * 64 + (lane & 7) + (lane >> 4) * 8;         // + jp*16
    const int uB = (lane >> 3) & 1;
    const uint32_t swz = (uint32_t)(lane & 7);
    const int g = lane >> 2;
    const int t = lane & 3;

    float c[4][8][4];
    #pragma unroll
    for (int i = 0; i < 4; i++)
        #pragma unroll
        for (int j = 0; j < 8; j++)
            #pragma unroll
            for (int q = 0; q < 4; q++) c[i][j][q] = 0.f;

    uint32_t a[2][4][4], b[2][4][4];

    // prologue: stages (w0,s0) and (w0,s1)
    load_stage(0, 0, 0); CP_COMMIT();
    load_stage(0, 1, 1); CP_COMMIT();
    int wl = 0, slc = 2, slot_l = 2;   // next stage to load
    int slot_c = 0;                    // stage being computed

    for (int w = 0; w < nt; w++) {
        const int by = ids[w] >> 2;
        const int bx = ids[w] & 3;

        for (int s = 0; s < NSST; s++) {
            CP_WAIT_1();
            __syncthreads();                 // stage (w,s) visible; slot_l free
            if (wl < nt) {
                load_stage(wl, slc, slot_l);
                if (++slc == NSST) { slc = 0; wl++; }
                if (++slot_l == RING) slot_l = 0;
            }
            CP_COMMIT();                     // empty group when drained

            const uint32_t ab = sb + (uint32_t)slot_c * STAGEB;
            const uint32_t bb = ab + ATILEB;
            if (++slot_c == RING) slot_c = 0;

            // kk=0 fragments
            #pragma unroll
            for (int i = 0; i < 4; i++) {
                const uint32_t addr = ab + (uint32_t)(rA + i * 16) * 128
                    + ((((uint32_t)uA) ^ swz) << 4);
                LDSM_X4(a[0][i][0], a[0][i][1], a[0][i][2], a[0][i][3], addr);
            }
            #pragma unroll
            for (int jp = 0; jp < 4; jp++) {
                const uint32_t addr = bb + (uint32_t)(rB + jp * 16) * 128
                    + ((((uint32_t)uB) ^ swz) << 4);
                LDSM_X4(b[0][jp][0], b[0][jp][1], b[0][jp][2], b[0][jp][3], addr);
            }
            #pragma unroll
            for (int kk = 0; kk < 4; kk++) {
                const int fb = kk & 1;
                if (kk + 1 < 4) {            // prefetch next k16 fragments
                    #pragma unroll
                    for (int i = 0; i < 4; i++) {
                        const uint32_t addr = ab + (uint32_t)(rA + i * 16) * 128
                            + ((((uint32_t)((kk + 1) * 2 + uA)) ^ swz) << 4);
                        LDSM_X4(a[fb ^ 1][i][0], a[fb ^ 1][i][1],
                                a[fb ^ 1][i][2], a[fb ^ 1][i][3], addr);
                    }
                    #pragma unroll
                    for (int jp = 0; jp < 4; jp++) {
                        const uint32_t addr = bb + (uint32_t)(rB + jp * 16) * 128
                            + ((((uint32_t)((kk + 1) * 2 + uB)) ^ swz) << 4);
                        LDSM_X4(b[fb ^ 1][jp][0], b[fb ^ 1][jp][1],
                                b[fb ^ 1][jp][2], b[fb ^ 1][jp][3], addr);
                    }
                }
                #pragma unroll
                for (int i = 0; i < 4; i++) {
                    #pragma unroll
                    for (int jp = 0; jp < 4; jp++) {
                        MMA_F16(c[i][jp * 2][0], c[i][jp * 2][1],
                                c[i][jp * 2][2], c[i][jp * 2][3],
                                a[fb][i][0], a[fb][i][1], a[fb][i][2], a[fb][i][3],
                                b[fb][jp][0], b[fb][jp][1]);
                        MMA_F16(c[i][jp * 2 + 1][0], c[i][jp * 2 + 1][1],
                                c[i][jp * 2 + 1][2], c[i][jp * 2 + 1][3],
                                a[fb][i][0], a[fb][i][1], a[fb][i][2], a[fb][i][3],
                                b[fb][jp][2], b[fb][jp][3]);
                    }
                }
            }
        }

        // ---- epilogue for tile w (overlaps next tile's in-flight loads) ----
        #pragma unroll
        for (int i = 0; i < 4; i++) {
            const int mg0 = by * BM + wm * 64 + i * 16 + g;
            const float x0 = g_xsq[mg0];
            const float x1 = g_xsq[mg0 + 8];
            float* row0 = C + (size_t)mg0 * P_;
            float* row1 = C + (size_t)(mg0 + 8) * P_;
            #pragma unroll
            for (int j = 0; j < 8; j++) {
                const int ng = bx * BN + wn * 64 + j * 8 + 2 * t;
                const float p0 = g_psq[ng];
                const float p1 = g_psq[ng + 1];
                float2 v0, v1;
                v0.x = x0 + p0 - 2.f * c[i][j][0];
                v0.y = x0 + p1 - 2.f * c[i][j][1];
                v1.x = x1 + p0 - 2.f * c[i][j][2];
                v1.y = x1 + p1 - 2.f * c[i][j][3];
                *reinterpret_cast<float2*>(row0 + ng) = v0;
                *reinterpret_cast<float2*>(row1 + ng) = v1;
                c[i][j][0] = 0.f; c[i][j][1] = 0.f;
                c[i][j][2] = 0.f; c[i][j][3] = 0.f;
            }
        }
    }
}

// ---------------------------------------------------------------------------
extern "C" void kernel_launch(void* const* d_in, const int* in_sizes, int n_in,
                              void* d_out, int out_size) {
    const float* inputs = (const float*)d_in[0];   // [M_, D_]
    const float* protos = (const float*)d_in[1];   // [P_, D_]
    float* out = (float*)d_out;

    // 1) fp16 copies + exact f32 norms + prototype passthrough (single pass)
    prep_kernel<<<(M_ + P_) / 16, 256>>>(inputs, protos, out + (size_t)M_ * P_);

    // 2) persistent fused distance GEMM
    cudaFuncSetAttribute(dist_f16_p_kernel,
                         cudaFuncAttributeMaxDynamicSharedMemorySize, SMEM_BYTES);
    dist_f16_p_kernel<<<GRID, NTH, SMEM_BYTES>>>(out);
}